// round 1
// baseline (speedup 1.0000x reference)
#include <cuda_runtime.h>
#include <cub/cub.cuh>
#include <cstdint>
#include <climits>

// Problem constants (fixed instance)
#define B     4
#define NLID  16384
#define NIMG  4096
#define NTOK  20480          // NLID + NIMG
#define C     256
#define NV    6
#define TOTAL (B*NTOK)       // 81920

// ---------------- static device scratch (no allocations allowed) ----------------
__device__ unsigned long long g_keys[TOTAL];
__device__ unsigned long long g_keys_out[TOTAL];
__device__ unsigned char      g_temp[8u << 20];   // 8 MB CUB temp storage
__device__ int                g_min[B][3];
__device__ int                g_max[B][3];
__device__ float              g_invK[B][NV][9];
__device__ float              g_invR[B][NV][9];
__device__ int4               g_q[TOTAL];

// ---------------- 3x3 inverse via adjugate in double ----------------
__device__ __forceinline__ void inv3(const float* a, float* o) {
    double m[9];
#pragma unroll
    for (int i = 0; i < 9; i++) m[i] = (double)a[i];
    double c00 =   m[4]*m[8] - m[5]*m[7];
    double c01 = -(m[3]*m[8] - m[5]*m[6]);
    double c02 =   m[3]*m[7] - m[4]*m[6];
    double det = m[0]*c00 + m[1]*c01 + m[2]*c02;
    double id  = 1.0 / det;
    o[0] = (float)( c00 * id);
    o[1] = (float)(-(m[1]*m[8] - m[2]*m[7]) * id);
    o[2] = (float)( (m[1]*m[5] - m[2]*m[4]) * id);
    o[3] = (float)( c01 * id);
    o[4] = (float)( (m[0]*m[8] - m[2]*m[6]) * id);
    o[5] = (float)(-(m[0]*m[5] - m[2]*m[3]) * id);
    o[6] = (float)( c02 * id);
    o[7] = (float)(-(m[0]*m[7] - m[1]*m[6]) * id);
    o[8] = (float)( (m[0]*m[4] - m[1]*m[3]) * id);
}

// ---------------- init: min/max identities + trailing scalars ----------------
__global__ void init_kernel(float* out, int out_size) {
    int t = threadIdx.x;
    if (t < B * 3) {
        ((int*)g_min)[t] = INT_MAX;
        ((int*)g_max)[t] = INT_MIN;
    }
    if (t == 0) {
        size_t base = (size_t)TOTAL * C + 2 * (size_t)TOTAL;
        if ((size_t)out_size >= base + 2) {
            out[base + 0] = 16384.0f;   // lidar_tokens.shape[1]
            out[base + 1] = 1.0f;
        }
    }
}

// ---------------- per-(b,view) matrix inverses ----------------
__global__ void mat_kernel(const float* __restrict__ K, const float* __restrict__ R) {
    int t = threadIdx.x;
    if (t >= B * NV) return;
    int b = t / NV, v = t % NV;
    inv3(K + (size_t)t * 9, g_invK[b][v]);
    inv3(R + (size_t)t * 9, g_invR[b][v]);
}

// ---------------- quantize + per-batch min/max ----------------
__global__ void q_kernel(const float* __restrict__ lidar_coords,
                         const float* __restrict__ img_kuvd,
                         const float* __restrict__ T,
                         const float* __restrict__ post_trans) {
    int b = blockIdx.y;
    int i = blockIdx.x * blockDim.x + threadIdx.x;   // < NTOK

    float x, y, z;
    if (i < NLID) {
        const float* c = lidar_coords + ((size_t)b * NLID + i) * 3;
        x = c[0]; y = c[1]; z = c[2];
    } else {
        int j = i - NLID;
        const float* kv = img_kuvd + ((size_t)b * NIMG + j) * 4;
        int cam = (int)kv[0];
        float u = kv[1], v = kv[2], D = kv[3];
        const float* tt = post_trans + (b * NV + cam) * 3;
        float u1 = u - tt[0], v1 = v - tt[1], w1 = 1.0f - tt[2];
        const float* iR = g_invR[b][cam];
        float rx = fmaf(iR[0], u1, fmaf(iR[1], v1, iR[2] * w1));
        float ry = fmaf(iR[3], u1, fmaf(iR[4], v1, iR[5] * w1));
        const float* iK = g_invK[b][cam];
        float cx = fmaf(iK[0], rx, fmaf(iK[1], ry, iK[2])) * D;
        float cy = fmaf(iK[3], rx, fmaf(iK[4], ry, iK[5])) * D;
        float cz = fmaf(iK[6], rx, fmaf(iK[7], ry, iK[8])) * D;
        const float* Tm = T + (size_t)(b * NV + cam) * 16;
        x = fmaf(Tm[0], cx, fmaf(Tm[1], cy, fmaf(Tm[2],  cz, Tm[3])));
        y = fmaf(Tm[4], cx, fmaf(Tm[5], cy, fmaf(Tm[6],  cz, Tm[7])));
        z = fmaf(Tm[8], cx, fmaf(Tm[9], cy, fmaf(Tm[10], cz, Tm[11])));
    }
    int q0 = (int)floorf(x), q1 = (int)floorf(y), q2 = (int)floorf(z);
    g_q[b * NTOK + i] = make_int4(q0, q1, q2, 0);

    __shared__ int smin[3], smax[3];
    if (threadIdx.x < 3) { smin[threadIdx.x] = INT_MAX; smax[threadIdx.x] = INT_MIN; }
    __syncthreads();
    atomicMin(&smin[0], q0); atomicMax(&smax[0], q0);
    atomicMin(&smin[1], q1); atomicMax(&smax[1], q1);
    atomicMin(&smin[2], q2); atomicMax(&smax[2], q2);
    __syncthreads();
    if (threadIdx.x < 3) {
        atomicMin(&g_min[b][threadIdx.x], smin[threadIdx.x]);
        atomicMax(&g_max[b][threadIdx.x], smax[threadIdx.x]);
    }
}

// ---------------- build composite sort keys ----------------
__global__ void key_kernel(const unsigned char* __restrict__ lmask,
                           const unsigned char* __restrict__ imask) {
    int gid = blockIdx.x * blockDim.x + threadIdx.x;
    if (gid >= TOTAL) return;
    int b = gid / NTOK, i = gid % NTOK;
    int4 q = g_q[gid];
    int m0 = g_min[b][0], m1 = g_min[b][1], m2 = g_min[b][2];
    int d0 = q.x - m0, d1 = q.y - m1, d2 = q.z - m2;
    int M1 = g_max[b][1] - m1;
    int M2 = g_max[b][2] - m2;
    int s1 = (d0 & 1)        ? (M1 - d1) : d1;           // snake along d1
    int s2 = ((d0 + d1) & 1) ? (M2 - d2) : d2;           // snake along d2 (uses raw d1)
    bool mask = (i < NLID) ? (lmask[(size_t)b * NLID + i] != 0)
                           : (imask[(size_t)b * NIMG + (i - NLID)] != 0);
    unsigned long long key;
    if (mask) {
        key = ((unsigned long long)b << 46) | (0x3FFFFFFFull << 16) | (unsigned)i;
    } else {
        key = ((unsigned long long)b  << 46)
            | ((unsigned long long)d0 << 36)
            | ((unsigned long long)s1 << 26)
            | ((unsigned long long)s2 << 16)
            | (unsigned)i;
    }
    g_keys[gid] = key;
}

// ---------------- gather rows + write idx/mask outputs ----------------
__global__ void gather_kernel(const float* __restrict__ lidar_tokens,
                              const float* __restrict__ img_tokens,
                              const unsigned char* __restrict__ lmask,
                              const unsigned char* __restrict__ imask,
                              float* __restrict__ out) {
    long long gid = (long long)blockIdx.x * blockDim.x + threadIdx.x;  // TOTAL*64 threads
    int r  = (int)(gid >> 6);
    int c4 = (int)(gid & 63);
    if (r >= TOTAL) return;
    unsigned long long key = g_keys_out[r];
    int idx = (int)(key & 0xFFFFull);
    int b = r / NTOK;
    const float4* src;
    if (idx < NLID)
        src = (const float4*)(lidar_tokens + ((size_t)b * NLID + idx) * C);
    else
        src = (const float4*)(img_tokens + ((size_t)b * NIMG + (idx - NLID)) * C);
    ((float4*)out)[(size_t)r * 64 + c4] = src[c4];

    if (c4 == 0) {
        size_t idx_base  = (size_t)TOTAL * C;
        size_t mask_base = idx_base + TOTAL;
        out[idx_base + r] = (float)idx;
        bool m = (idx < NLID) ? (lmask[(size_t)b * NLID + idx] != 0)
                              : (imask[(size_t)b * NIMG + (idx - NLID)] != 0);
        out[mask_base + r] = m ? 1.0f : 0.0f;
    }
}

// ---------------- launch ----------------
extern "C" void kernel_launch(void* const* d_in, const int* in_sizes, int n_in,
                              void* d_out, int out_size) {
    const float* lidar_tokens = (const float*)d_in[0];
    const float* lidar_coords = (const float*)d_in[1];
    const float* img_tokens   = (const float*)d_in[2];
    const float* img_kuvd     = (const float*)d_in[3];
    const float* Km           = (const float*)d_in[4];
    const float* Tm           = (const float*)d_in[5];
    const float* Rm           = (const float*)d_in[6];
    const float* ptrans       = (const float*)d_in[7];
    const unsigned char* lm   = (const unsigned char*)d_in[8];
    const unsigned char* im   = (const unsigned char*)d_in[9];
    float* out = (float*)d_out;

    init_kernel<<<1, 32>>>(out, out_size);
    mat_kernel<<<1, 32>>>(Km, Rm);

    dim3 gq(NTOK / 256, B);
    q_kernel<<<gq, 256>>>(lidar_coords, img_kuvd, Tm, ptrans);

    key_kernel<<<(TOTAL + 255) / 256, 256>>>(lm, im);

    void *keys_p, *keys_out_p, *temp_p;
    cudaGetSymbolAddress(&keys_p, g_keys);
    cudaGetSymbolAddress(&keys_out_p, g_keys_out);
    cudaGetSymbolAddress(&temp_p, g_temp);
    size_t temp_bytes = sizeof(g_temp);
    // Stable LSD radix over bits [16,48): (b | d0 | s1 | s2); idx in low bits
    // rides along untouched -> stable tie-break by original index.
    cub::DeviceRadixSort::SortKeys(temp_p, temp_bytes,
                                   (const unsigned long long*)keys_p,
                                   (unsigned long long*)keys_out_p,
                                   TOTAL, 16, 48);

    gather_kernel<<<(TOTAL * 64) / 256, 256>>>(lidar_tokens, img_tokens, lm, im, out);
}